// round 7
// baseline (speedup 1.0000x reference)
#include <cuda_runtime.h>
#include <cstdint>
#include <cstddef>

#define SEQ   4096
#define BATCH 4
#define DE    1024
#define DH    128

// flash-attention tiling
#define BR 64
#define BC 64
#define QPAD 132
#define KPAD 132
#define PPAD 68

// projection tiling
#define PROJ_PAD 36

// scratch for q,k,v: [BATCH*SEQ, DH] fp32 each (8 MB apiece, static device mem — no allocs)
__device__ float g_q[BATCH * SEQ * DH];
__device__ float g_k[BATCH * SEQ * DH];
__device__ float g_v[BATCH * SEQ * DH];

// round-to-nearest fp32 -> tf32 (bit pattern in a 32-bit reg). RNA avoids the
// systematic truncation bias of feeding raw fp32 to the tf32 MMA.
__device__ __forceinline__ unsigned f2tf(float x) {
    unsigned u;
    asm("cvt.rna.tf32.f32 %0, %1;" : "=r"(u) : "f"(x));
    return u;
}

__device__ __forceinline__ void mma_tf32(float c[4], const unsigned a[4], const unsigned b[2]) {
    asm volatile(
        "mma.sync.aligned.m16n8k8.row.col.f32.tf32.tf32.f32 "
        "{%0,%1,%2,%3}, {%4,%5,%6,%7}, {%8,%9}, {%0,%1,%2,%3};\n"
        : "+f"(c[0]), "+f"(c[1]), "+f"(c[2]), "+f"(c[3])
        : "r"(a[0]), "r"(a[1]), "r"(a[2]), "r"(a[3]), "r"(b[0]), "r"(b[1]));
}

// ---------------------------------------------------------------------------
// QKV projection: out[m, h] = sum_e x[m, e] * W[h, e]
// M = BATCH*SEQ = 16384, N = 128 (one head), K = 1024. grid = (128 m-tiles, 3)
// CTA tile 128x128, k-chunk 32, 8 warps in a 4(m) x 2(n) grid, warp tile 32x64.
// ---------------------------------------------------------------------------
__global__ void __launch_bounds__(256) qkv_proj_kernel(
    const float* __restrict__ x,
    const float* __restrict__ Wq,
    const float* __restrict__ Wk,
    const float* __restrict__ Wv)
{
    __shared__ float sA[128 * PROJ_PAD];   // x tile   [128 m][32 k]
    __shared__ float sB[128 * PROJ_PAD];   // W tile   [128 n][32 k]

    const float* W  = (blockIdx.y == 0) ? Wq : (blockIdx.y == 1) ? Wk : Wv;
    float*       out = (blockIdx.y == 0) ? g_q : (blockIdx.y == 1) ? g_k : g_v;

    const int m0   = blockIdx.x * 128;
    const int tid  = threadIdx.x;
    const int lane = tid & 31;
    const int w    = tid >> 5;
    const int wm   = w & 3;    // m-offset wm*32
    const int wn   = w >> 2;   // n-offset wn*64

    float acc[2][8][4];
    #pragma unroll
    for (int mt = 0; mt < 2; mt++)
        #pragma unroll
        for (int nt = 0; nt < 8; nt++)
            #pragma unroll
            for (int i = 0; i < 4; i++) acc[mt][nt][i] = 0.f;

    for (int kc = 0; kc < DE; kc += 32) {
        __syncthreads();   // previous iteration's reads done before overwrite
        #pragma unroll
        for (int i = 0; i < 4; i++) {
            const int idx = tid + i * 256;        // 0..1023 float4 slots
            const int r = idx >> 3;               // 0..127
            const int c = (idx & 7) << 2;         // 0..28
            float4 v = *(const float4*)(x + (size_t)(m0 + r) * DE + kc + c);
            float* d = &sA[r * PROJ_PAD + c];
            d[0] = __uint_as_float(f2tf(v.x));
            d[1] = __uint_as_float(f2tf(v.y));
            d[2] = __uint_as_float(f2tf(v.z));
            d[3] = __uint_as_float(f2tf(v.w));
            float4 u = *(const float4*)(W + (size_t)r * DE + kc + c);
            float* e = &sB[r * PROJ_PAD + c];
            e[0] = __uint_as_float(f2tf(u.x));
            e[1] = __uint_as_float(f2tf(u.y));
            e[2] = __uint_as_float(f2tf(u.z));
            e[3] = __uint_as_float(f2tf(u.w));
        }
        __syncthreads();

        #pragma unroll
        for (int ks = 0; ks < 4; ks++) {
            const int c = ks * 8 + (lane & 3);
            unsigned a[2][4];
            #pragma unroll
            for (int mt = 0; mt < 2; mt++) {
                const int r = wm * 32 + mt * 16 + (lane >> 2);
                a[mt][0] = __float_as_uint(sA[r * PROJ_PAD + c]);
                a[mt][1] = __float_as_uint(sA[(r + 8) * PROJ_PAD + c]);
                a[mt][2] = __float_as_uint(sA[r * PROJ_PAD + c + 4]);
                a[mt][3] = __float_as_uint(sA[(r + 8) * PROJ_PAD + c + 4]);
            }
            #pragma unroll
            for (int nt = 0; nt < 8; nt++) {
                const int n = wn * 64 + nt * 8 + (lane >> 2);
                unsigned b[2];
                b[0] = __float_as_uint(sB[n * PROJ_PAD + c]);
                b[1] = __float_as_uint(sB[n * PROJ_PAD + c + 4]);
                mma_tf32(acc[0][nt], a[0], b);
                mma_tf32(acc[1][nt], a[1], b);
            }
        }
    }

    // epilogue: fp32 to scratch
    #pragma unroll
    for (int mt = 0; mt < 2; mt++) {
        const int r = m0 + wm * 32 + mt * 16 + (lane >> 2);
        #pragma unroll
        for (int nt = 0; nt < 8; nt++) {
            const int c = wn * 64 + nt * 8 + 2 * (lane & 3);
            *(float2*)(out + (size_t)r * DH + c)       = make_float2(acc[mt][nt][0], acc[mt][nt][1]);
            *(float2*)(out + (size_t)(r + 8) * DH + c) = make_float2(acc[mt][nt][2], acc[mt][nt][3]);
        }
    }
}

// ---------------------------------------------------------------------------
// Flash attention: per CTA one (batch, 64-query-row) tile, loop over 64-key
// tiles of the full 4096 sequence. 4 warps; warp w owns query rows [16w,16w+16).
// K and V share one smem buffer (no pipelining yet). P goes through padded
// smem to re-fragment accumulator layout -> A-fragment layout for the PV mma.
// ---------------------------------------------------------------------------
__global__ void __launch_bounds__(128) attn_kernel(float* __restrict__ out)
{
    extern __shared__ float sm[];
    float* sQ  = sm;                    // [BR][QPAD]
    float* sKV = sQ + BR * QPAD;        // [BC][KPAD]
    float* sP  = sKV + BC * KPAD;       // [BR][PPAD]

    const int b    = blockIdx.y;
    const int qt   = blockIdx.x;
    const int tid  = threadIdx.x;
    const int lane = tid & 31;
    const int w    = tid >> 5;

    const float* Qg = g_q + ((size_t)b * SEQ + (size_t)qt * BR) * DH;
    const float* Kg = g_k + (size_t)b * SEQ * DH;
    const float* Vg = g_v + (size_t)b * SEQ * DH;

    // 1/(sqrt(DH)*sqrt(DE)) * log2(e), folded into Q so softmax uses exp2
    const float qscale = 1.4426950408889634f / 362.03867196751236f;

    // stage Q (scaled + tf32-rounded)
    for (int i = tid; i < BR * DH / 4; i += 128) {
        const int r = i >> 5;             // 32 float4 per row
        const int c = (i & 31) << 2;
        float4 v = *(const float4*)(Qg + (size_t)r * DH + c);
        float* d = &sQ[r * QPAD + c];
        d[0] = __uint_as_float(f2tf(v.x * qscale));
        d[1] = __uint_as_float(f2tf(v.y * qscale));
        d[2] = __uint_as_float(f2tf(v.z * qscale));
        d[3] = __uint_as_float(f2tf(v.w * qscale));
    }

    float acc[16][4];
    #pragma unroll
    for (int nt = 0; nt < 16; nt++)
        #pragma unroll
        for (int i = 0; i < 4; i++) acc[nt][i] = 0.f;
    float m0f = -INFINITY, m1f = -INFINITY;   // running max, rows (g) and (g+8)
    float l0 = 0.f, l1 = 0.f;                 // running denom

    __syncthreads();   // sQ visible (also covers first sKV write ordering)

    for (int kt = 0; kt < SEQ / BC; kt++) {
        // ---- load K tile (tf32-rounded) ----
        const float* Kt = Kg + (size_t)kt * BC * DH;
        for (int i = tid; i < BC * DH / 4; i += 128) {
            const int r = i >> 5;
            const int c = (i & 31) << 2;
            float4 v = *(const float4*)(Kt + (size_t)r * DH + c);
            float* d = &sKV[r * KPAD + c];
            d[0] = __uint_as_float(f2tf(v.x));
            d[1] = __uint_as_float(f2tf(v.y));
            d[2] = __uint_as_float(f2tf(v.z));
            d[3] = __uint_as_float(f2tf(v.w));
        }
        __syncthreads();

        // ---- S = Q K^T (scaled), warp strip 16 x 64 ----
        float s[8][4];
        #pragma unroll
        for (int nt = 0; nt < 8; nt++)
            #pragma unroll
            for (int i = 0; i < 4; i++) s[nt][i] = 0.f;

        #pragma unroll
        for (int ks = 0; ks < DH / 8; ks++) {
            const int c = ks * 8 + (lane & 3);
            const int r = w * 16 + (lane >> 2);
            unsigned a[4];
            a[0] = __float_as_uint(sQ[r * QPAD + c]);
            a[1] = __float_as_uint(sQ[(r + 8) * QPAD + c]);
            a[2] = __float_as_uint(sQ[r * QPAD + c + 4]);
            a[3] = __float_as_uint(sQ[(r + 8) * QPAD + c + 4]);
            #pragma unroll
            for (int nt = 0; nt < 8; nt++) {
                const int n = nt * 8 + (lane >> 2);
                unsigned bb[2];
                bb[0] = __float_as_uint(sKV[n * KPAD + c]);
                bb[1] = __float_as_uint(sKV[n * KPAD + c + 4]);
                mma_tf32(s[nt], a, bb);
            }
        }
        __syncthreads();   // all warps done reading K

        // ---- load V tile into the same buffer (overlaps with softmax math) ----
        const float* Vt = Vg + (size_t)kt * BC * DH;
        for (int i = tid; i < BC * DH / 4; i += 128) {
            const int r = i >> 5;
            const int c = (i & 31) << 2;
            float4 v = *(const float4*)(Vt + (size_t)r * DH + c);
            float* d = &sKV[r * KPAD + c];
            d[0] = __uint_as_float(f2tf(v.x));
            d[1] = __uint_as_float(f2tf(v.y));
            d[2] = __uint_as_float(f2tf(v.z));
            d[3] = __uint_as_float(f2tf(v.w));
        }

        // ---- online softmax (register-resident, per quad = one row) ----
        float rmax0 = -INFINITY, rmax1 = -INFINITY;
        #pragma unroll
        for (int nt = 0; nt < 8; nt++) {
            rmax0 = fmaxf(rmax0, fmaxf(s[nt][0], s[nt][1]));
            rmax1 = fmaxf(rmax1, fmaxf(s[nt][2], s[nt][3]));
        }
        rmax0 = fmaxf(rmax0, __shfl_xor_sync(0xffffffffu, rmax0, 1));
        rmax0 = fmaxf(rmax0, __shfl_xor_sync(0xffffffffu, rmax0, 2));
        rmax1 = fmaxf(rmax1, __shfl_xor_sync(0xffffffffu, rmax1, 1));
        rmax1 = fmaxf(rmax1, __shfl_xor_sync(0xffffffffu, rmax1, 2));

        const float mnew0 = fmaxf(m0f, rmax0);
        const float mnew1 = fmaxf(m1f, rmax1);
        const float alpha0 = exp2f(m0f - mnew0);
        const float alpha1 = exp2f(m1f - mnew1);
        m0f = mnew0; m1f = mnew1;

        float rs0 = 0.f, rs1 = 0.f;
        const int prow = w * 16 + (lane >> 2);
        #pragma unroll
        for (int nt = 0; nt < 8; nt++) {
            const int pcol = nt * 8 + 2 * (lane & 3);
            // round P to tf32 BEFORE summing so l matches what the mma consumes
            float p0 = __uint_as_float(f2tf(exp2f(s[nt][0] - mnew0)));
            float p1 = __uint_as_float(f2tf(exp2f(s[nt][1] - mnew0)));
            float p2 = __uint_as_float(f2tf(exp2f(s[nt][2] - mnew1)));
            float p3 = __uint_as_float(f2tf(exp2f(s[nt][3] - mnew1)));
            rs0 += p0 + p1;
            rs1 += p2 + p3;
            sP[prow * PPAD + pcol]           = p0;
            sP[prow * PPAD + pcol + 1]       = p1;
            sP[(prow + 8) * PPAD + pcol]     = p2;
            sP[(prow + 8) * PPAD + pcol + 1] = p3;
        }
        rs0 += __shfl_xor_sync(0xffffffffu, rs0, 1);
        rs0 += __shfl_xor_sync(0xffffffffu, rs0, 2);
        rs1 += __shfl_xor_sync(0xffffffffu, rs1, 1);
        rs1 += __shfl_xor_sync(0xffffffffu, rs1, 2);
        l0 = l0 * alpha0 + rs0;
        l1 = l1 * alpha1 + rs1;

        #pragma unroll
        for (int nt = 0; nt < 16; nt++) {
            acc[nt][0] *= alpha0;
            acc[nt][1] *= alpha0;
            acc[nt][2] *= alpha1;
            acc[nt][3] *= alpha1;
        }

        __syncthreads();   // V visible, sP (own warp) visible

        // ---- acc += P @ V ----
        #pragma unroll
        for (int ks = 0; ks < BC / 8; ks++) {
            const int c = ks * 8 + (lane & 3);
            const int r = w * 16 + (lane >> 2);
            unsigned a[4];
            a[0] = __float_as_uint(sP[r * PPAD + c]);
            a[1] = __float_as_uint(sP[(r + 8) * PPAD + c]);
            a[2] = __float_as_uint(sP[r * PPAD + c + 4]);
            a[3] = __float_as_uint(sP[(r + 4) * PPAD + c + 4 - 4 * PPAD + 4 * PPAD]);
            // (identical to sP[(r+8)*PPAD+c+4]; kept simple below)
            a[3] = __float_as_uint(sP[(r + 8) * PPAD + c + 4]);
            #pragma unroll
            for (int nt = 0; nt < 16; nt++) {
                const int n = nt * 8 + (lane >> 2);
                unsigned bb[2];
                bb[0] = __float_as_uint(sKV[c * KPAD + n]);
                bb[1] = __float_as_uint(sKV[(c + 4) * KPAD + n]);
                mma_tf32(acc[nt], a, bb);
            }
        }
        __syncthreads();   // all warps done reading V before next K load
    }

    // ---- epilogue: out = acc / l ----
    const float inv0 = 1.f / l0;
    const float inv1 = 1.f / l1;
    const int r = qt * BR + w * 16 + (lane >> 2);
    float* Ob = out + (size_t)b * SEQ * DH;
    #pragma unroll
    for (int nt = 0; nt < 16; nt++) {
        const int c = nt * 8 + 2 * (lane & 3);
        *(float2*)(Ob + (size_t)r * DH + c)       = make_float2(acc[nt][0] * inv0, acc[nt][1] * inv0);
        *(float2*)(Ob + (size_t)(r + 8) * DH + c) = make_float2(acc[nt][2] * inv1, acc[nt][3] * inv1);
    }
}

// ---------------------------------------------------------------------------
extern "C" void kernel_launch(void* const* d_in, const int* in_sizes, int n_in,
                              void* d_out, int out_size)
{
    (void)in_sizes; (void)n_in; (void)out_size;
    const float* x  = (const float*)d_in[0];
    const float* Wq = (const float*)d_in[1];
    const float* Wk = (const float*)d_in[2];
    const float* Wv = (const float*)d_in[3];
    float* out = (float*)d_out;

    const int attn_smem = (BR * QPAD + BC * KPAD + BR * PPAD) * (int)sizeof(float); // 84992 B
    (void)cudaFuncSetAttribute(attn_kernel, cudaFuncAttributeMaxDynamicSharedMemorySize, attn_smem);

    qkv_proj_kernel<<<dim3((BATCH * SEQ) / 128, 3), 256>>>(x, Wq, Wk, Wv);
    attn_kernel<<<dim3(SEQ / BR, BATCH), 128, attn_smem>>>(out);
}

// round 8
// speedup vs baseline: 1.0001x; 1.0001x over previous
#include <cuda_runtime.h>
#include <cstdint>
#include <cstddef>

#define SEQ   4096
#define BATCH 4
#define DE    1024
#define DH    128

// flash-attention tiling
#define BR 64
#define BC 64
#define QPAD 132
#define KPAD 132
#define PPAD 68

// projection tiling
#define PROJ_PAD 36

// scratch for q,k,v: [BATCH*SEQ, DH] fp32 each (8 MB apiece, static device mem — no allocs)
__device__ float g_q[BATCH * SEQ * DH];
__device__ float g_k[BATCH * SEQ * DH];
__device__ float g_v[BATCH * SEQ * DH];

// round-to-nearest fp32 -> tf32 (bit pattern in a 32-bit reg). RNA avoids the
// systematic truncation bias of feeding raw fp32 to the tf32 MMA.
__device__ __forceinline__ unsigned f2tf(float x) {
    unsigned u;
    asm("cvt.rna.tf32.f32 %0, %1;" : "=r"(u) : "f"(x));
    return u;
}

__device__ __forceinline__ void mma_tf32(float c[4], const unsigned a[4], const unsigned b[2]) {
    asm volatile(
        "mma.sync.aligned.m16n8k8.row.col.f32.tf32.tf32.f32 "
        "{%0,%1,%2,%3}, {%4,%5,%6,%7}, {%8,%9}, {%0,%1,%2,%3};\n"
        : "+f"(c[0]), "+f"(c[1]), "+f"(c[2]), "+f"(c[3])
        : "r"(a[0]), "r"(a[1]), "r"(a[2]), "r"(a[3]), "r"(b[0]), "r"(b[1]));
}

// ---------------------------------------------------------------------------
// QKV projection: out[m, h] = sum_e x[m, e] * W[h, e]
// M = BATCH*SEQ = 16384, N = 128 (one head), K = 1024. grid = (128 m-tiles, 3)
// CTA tile 128x128, k-chunk 32, 8 warps in a 4(m) x 2(n) grid, warp tile 32x64.
// ---------------------------------------------------------------------------
__global__ void __launch_bounds__(256) qkv_proj_kernel(
    const float* __restrict__ x,
    const float* __restrict__ Wq,
    const float* __restrict__ Wk,
    const float* __restrict__ Wv)
{
    __shared__ float sA[128 * PROJ_PAD];   // x tile   [128 m][32 k]
    __shared__ float sB[128 * PROJ_PAD];   // W tile   [128 n][32 k]

    const float* W  = (blockIdx.y == 0) ? Wq : (blockIdx.y == 1) ? Wk : Wv;
    float*       out = (blockIdx.y == 0) ? g_q : (blockIdx.y == 1) ? g_k : g_v;

    const int m0   = blockIdx.x * 128;
    const int tid  = threadIdx.x;
    const int lane = tid & 31;
    const int w    = tid >> 5;
    const int wm   = w & 3;    // m-offset wm*32
    const int wn   = w >> 2;   // n-offset wn*64

    float acc[2][8][4];
    #pragma unroll
    for (int mt = 0; mt < 2; mt++)
        #pragma unroll
        for (int nt = 0; nt < 8; nt++)
            #pragma unroll
            for (int i = 0; i < 4; i++) acc[mt][nt][i] = 0.f;

    for (int kc = 0; kc < DE; kc += 32) {
        __syncthreads();   // previous iteration's reads done before overwrite
        #pragma unroll
        for (int i = 0; i < 4; i++) {
            const int idx = tid + i * 256;        // 0..1023 float4 slots
            const int r = idx >> 3;               // 0..127
            const int c = (idx & 7) << 2;         // 0..28
            float4 v = *(const float4*)(x + (size_t)(m0 + r) * DE + kc + c);
            float* d = &sA[r * PROJ_PAD + c];
            d[0] = __uint_as_float(f2tf(v.x));
            d[1] = __uint_as_float(f2tf(v.y));
            d[2] = __uint_as_float(f2tf(v.z));
            d[3] = __uint_as_float(f2tf(v.w));
            float4 u = *(const float4*)(W + (size_t)r * DE + kc + c);
            float* e = &sB[r * PROJ_PAD + c];
            e[0] = __uint_as_float(f2tf(u.x));
            e[1] = __uint_as_float(f2tf(u.y));
            e[2] = __uint_as_float(f2tf(u.z));
            e[3] = __uint_as_float(f2tf(u.w));
        }
        __syncthreads();

        #pragma unroll
        for (int ks = 0; ks < 4; ks++) {
            const int c = ks * 8 + (lane & 3);
            unsigned a[2][4];
            #pragma unroll
            for (int mt = 0; mt < 2; mt++) {
                const int r = wm * 32 + mt * 16 + (lane >> 2);
                a[mt][0] = __float_as_uint(sA[r * PROJ_PAD + c]);
                a[mt][1] = __float_as_uint(sA[(r + 8) * PROJ_PAD + c]);
                a[mt][2] = __float_as_uint(sA[r * PROJ_PAD + c + 4]);
                a[mt][3] = __float_as_uint(sA[(r + 8) * PROJ_PAD + c + 4]);
            }
            #pragma unroll
            for (int nt = 0; nt < 8; nt++) {
                const int n = wn * 64 + nt * 8 + (lane >> 2);
                unsigned b[2];
                b[0] = __float_as_uint(sB[n * PROJ_PAD + c]);
                b[1] = __float_as_uint(sB[n * PROJ_PAD + c + 4]);
                mma_tf32(acc[0][nt], a[0], b);
                mma_tf32(acc[1][nt], a[1], b);
            }
        }
    }

    // epilogue: fp32 to scratch
    #pragma unroll
    for (int mt = 0; mt < 2; mt++) {
        const int r = m0 + wm * 32 + mt * 16 + (lane >> 2);
        #pragma unroll
        for (int nt = 0; nt < 8; nt++) {
            const int c = wn * 64 + nt * 8 + 2 * (lane & 3);
            *(float2*)(out + (size_t)r * DH + c)       = make_float2(acc[mt][nt][0], acc[mt][nt][1]);
            *(float2*)(out + (size_t)(r + 8) * DH + c) = make_float2(acc[mt][nt][2], acc[mt][nt][3]);
        }
    }
}

// ---------------------------------------------------------------------------
// Flash attention: per CTA one (batch, 64-query-row) tile, loop over 64-key
// tiles of the full 4096 sequence. 4 warps; warp w owns query rows [16w,16w+16).
// K and V share one smem buffer (no pipelining yet). P goes through padded
// smem to re-fragment accumulator layout -> A-fragment layout for the PV mma.
// ---------------------------------------------------------------------------
__global__ void __launch_bounds__(128) attn_kernel(float* __restrict__ out)
{
    extern __shared__ float sm[];
    float* sQ  = sm;                    // [BR][QPAD]
    float* sKV = sQ + BR * QPAD;        // [BC][KPAD]
    float* sP  = sKV + BC * KPAD;       // [BR][PPAD]

    const int b    = blockIdx.y;
    const int qt   = blockIdx.x;
    const int tid  = threadIdx.x;
    const int lane = tid & 31;
    const int w    = tid >> 5;

    const float* Qg = g_q + ((size_t)b * SEQ + (size_t)qt * BR) * DH;
    const float* Kg = g_k + (size_t)b * SEQ * DH;
    const float* Vg = g_v + (size_t)b * SEQ * DH;

    // 1/(sqrt(DH)*sqrt(DE)) * log2(e), folded into Q so softmax uses exp2
    const float qscale = 1.4426950408889634f / 362.03867196751236f;

    // stage Q (scaled + tf32-rounded)
    for (int i = tid; i < BR * DH / 4; i += 128) {
        const int r = i >> 5;             // 32 float4 per row
        const int c = (i & 31) << 2;
        float4 v = *(const float4*)(Qg + (size_t)r * DH + c);
        float* d = &sQ[r * QPAD + c];
        d[0] = __uint_as_float(f2tf(v.x * qscale));
        d[1] = __uint_as_float(f2tf(v.y * qscale));
        d[2] = __uint_as_float(f2tf(v.z * qscale));
        d[3] = __uint_as_float(f2tf(v.w * qscale));
    }

    float acc[16][4];
    #pragma unroll
    for (int nt = 0; nt < 16; nt++)
        #pragma unroll
        for (int i = 0; i < 4; i++) acc[nt][i] = 0.f;
    float m0f = -INFINITY, m1f = -INFINITY;   // running max, rows (g) and (g+8)
    float l0 = 0.f, l1 = 0.f;                 // running denom

    __syncthreads();   // sQ visible (also covers first sKV write ordering)

    for (int kt = 0; kt < SEQ / BC; kt++) {
        // ---- load K tile (tf32-rounded) ----
        const float* Kt = Kg + (size_t)kt * BC * DH;
        for (int i = tid; i < BC * DH / 4; i += 128) {
            const int r = i >> 5;
            const int c = (i & 31) << 2;
            float4 v = *(const float4*)(Kt + (size_t)r * DH + c);
            float* d = &sKV[r * KPAD + c];
            d[0] = __uint_as_float(f2tf(v.x));
            d[1] = __uint_as_float(f2tf(v.y));
            d[2] = __uint_as_float(f2tf(v.z));
            d[3] = __uint_as_float(f2tf(v.w));
        }
        __syncthreads();

        // ---- S = Q K^T (scaled), warp strip 16 x 64 ----
        float s[8][4];
        #pragma unroll
        for (int nt = 0; nt < 8; nt++)
            #pragma unroll
            for (int i = 0; i < 4; i++) s[nt][i] = 0.f;

        #pragma unroll
        for (int ks = 0; ks < DH / 8; ks++) {
            const int c = ks * 8 + (lane & 3);
            const int r = w * 16 + (lane >> 2);
            unsigned a[4];
            a[0] = __float_as_uint(sQ[r * QPAD + c]);
            a[1] = __float_as_uint(sQ[(r + 8) * QPAD + c]);
            a[2] = __float_as_uint(sQ[r * QPAD + c + 4]);
            a[3] = __float_as_uint(sQ[(r + 8) * QPAD + c + 4]);
            #pragma unroll
            for (int nt = 0; nt < 8; nt++) {
                const int n = nt * 8 + (lane >> 2);
                unsigned bb[2];
                bb[0] = __float_as_uint(sKV[n * KPAD + c]);
                bb[1] = __float_as_uint(sKV[n * KPAD + c + 4]);
                mma_tf32(s[nt], a, bb);
            }
        }
        __syncthreads();   // all warps done reading K

        // ---- load V tile into the same buffer (overlaps with softmax math) ----
        const float* Vt = Vg + (size_t)kt * BC * DH;
        for (int i = tid; i < BC * DH / 4; i += 128) {
            const int r = i >> 5;
            const int c = (i & 31) << 2;
            float4 v = *(const float4*)(Vt + (size_t)r * DH + c);
            float* d = &sKV[r * KPAD + c];
            d[0] = __uint_as_float(f2tf(v.x));
            d[1] = __uint_as_float(f2tf(v.y));
            d[2] = __uint_as_float(f2tf(v.z));
            d[3] = __uint_as_float(f2tf(v.w));
        }

        // ---- online softmax (register-resident, per quad = one row) ----
        float rmax0 = -INFINITY, rmax1 = -INFINITY;
        #pragma unroll
        for (int nt = 0; nt < 8; nt++) {
            rmax0 = fmaxf(rmax0, fmaxf(s[nt][0], s[nt][1]));
            rmax1 = fmaxf(rmax1, fmaxf(s[nt][2], s[nt][3]));
        }
        rmax0 = fmaxf(rmax0, __shfl_xor_sync(0xffffffffu, rmax0, 1));
        rmax0 = fmaxf(rmax0, __shfl_xor_sync(0xffffffffu, rmax0, 2));
        rmax1 = fmaxf(rmax1, __shfl_xor_sync(0xffffffffu, rmax1, 1));
        rmax1 = fmaxf(rmax1, __shfl_xor_sync(0xffffffffu, rmax1, 2));

        const float mnew0 = fmaxf(m0f, rmax0);
        const float mnew1 = fmaxf(m1f, rmax1);
        const float alpha0 = exp2f(m0f - mnew0);
        const float alpha1 = exp2f(m1f - mnew1);
        m0f = mnew0; m1f = mnew1;

        float rs0 = 0.f, rs1 = 0.f;
        const int prow = w * 16 + (lane >> 2);
        #pragma unroll
        for (int nt = 0; nt < 8; nt++) {
            const int pcol = nt * 8 + 2 * (lane & 3);
            // round P to tf32 BEFORE summing so l matches what the mma consumes
            float p0 = __uint_as_float(f2tf(exp2f(s[nt][0] - mnew0)));
            float p1 = __uint_as_float(f2tf(exp2f(s[nt][1] - mnew0)));
            float p2 = __uint_as_float(f2tf(exp2f(s[nt][2] - mnew1)));
            float p3 = __uint_as_float(f2tf(exp2f(s[nt][3] - mnew1)));
            rs0 += p0 + p1;
            rs1 += p2 + p3;
            sP[prow * PPAD + pcol]           = p0;
            sP[prow * PPAD + pcol + 1]       = p1;
            sP[(prow + 8) * PPAD + pcol]     = p2;
            sP[(prow + 8) * PPAD + pcol + 1] = p3;
        }
        rs0 += __shfl_xor_sync(0xffffffffu, rs0, 1);
        rs0 += __shfl_xor_sync(0xffffffffu, rs0, 2);
        rs1 += __shfl_xor_sync(0xffffffffu, rs1, 1);
        rs1 += __shfl_xor_sync(0xffffffffu, rs1, 2);
        l0 = l0 * alpha0 + rs0;
        l1 = l1 * alpha1 + rs1;

        #pragma unroll
        for (int nt = 0; nt < 16; nt++) {
            acc[nt][0] *= alpha0;
            acc[nt][1] *= alpha0;
            acc[nt][2] *= alpha1;
            acc[nt][3] *= alpha1;
        }

        __syncthreads();   // V visible, sP (own warp) visible

        // ---- acc += P @ V ----
        #pragma unroll
        for (int ks = 0; ks < BC / 8; ks++) {
            const int c = ks * 8 + (lane & 3);
            const int r = w * 16 + (lane >> 2);
            unsigned a[4];
            a[0] = __float_as_uint(sP[r * PPAD + c]);
            a[1] = __float_as_uint(sP[(r + 8) * PPAD + c]);
            a[2] = __float_as_uint(sP[r * PPAD + c + 4]);
            a[3] = __float_as_uint(sP[(r + 4) * PPAD + c + 4 - 4 * PPAD + 4 * PPAD]);
            // (identical to sP[(r+8)*PPAD+c+4]; kept simple below)
            a[3] = __float_as_uint(sP[(r + 8) * PPAD + c + 4]);
            #pragma unroll
            for (int nt = 0; nt < 16; nt++) {
                const int n = nt * 8 + (lane >> 2);
                unsigned bb[2];
                bb[0] = __float_as_uint(sKV[c * KPAD + n]);
                bb[1] = __float_as_uint(sKV[(c + 4) * KPAD + n]);
                mma_tf32(acc[nt], a, bb);
            }
        }
        __syncthreads();   // all warps done reading V before next K load
    }

    // ---- epilogue: out = acc / l ----
    const float inv0 = 1.f / l0;
    const float inv1 = 1.f / l1;
    const int r = qt * BR + w * 16 + (lane >> 2);
    float* Ob = out + (size_t)b * SEQ * DH;
    #pragma unroll
    for (int nt = 0; nt < 16; nt++) {
        const int c = nt * 8 + 2 * (lane & 3);
        *(float2*)(Ob + (size_t)r * DH + c)       = make_float2(acc[nt][0] * inv0, acc[nt][1] * inv0);
        *(float2*)(Ob + (size_t)(r + 8) * DH + c) = make_float2(acc[nt][2] * inv1, acc[nt][3] * inv1);
    }
}

// ---------------------------------------------------------------------------
extern "C" void kernel_launch(void* const* d_in, const int* in_sizes, int n_in,
                              void* d_out, int out_size)
{
    (void)in_sizes; (void)n_in; (void)out_size;
    const float* x  = (const float*)d_in[0];
    const float* Wq = (const float*)d_in[1];
    const float* Wk = (const float*)d_in[2];
    const float* Wv = (const float*)d_in[3];
    float* out = (float*)d_out;

    const int attn_smem = (BR * QPAD + BC * KPAD + BR * PPAD) * (int)sizeof(float); // 84992 B
    (void)cudaFuncSetAttribute(attn_kernel, cudaFuncAttributeMaxDynamicSharedMemorySize, attn_smem);

    qkv_proj_kernel<<<dim3((BATCH * SEQ) / 128, 3), 256>>>(x, Wq, Wk, Wv);
    attn_kernel<<<dim3(SEQ / BR, BATCH), 128, attn_smem>>>(out);
}

// round 9
// speedup vs baseline: 1.0147x; 1.0146x over previous
#include <cuda_runtime.h>
#include <cstdint>
#include <cstddef>

#define SEQ   4096
#define BATCH 4
#define DE    1024
#define DH    128

// flash-attention tiling
#define BR 64
#define BC 64

// packed k-dim row strides (floats)
#define QSTR 136    // 128 data + 8 pad  (pairs (k,k+4) adjacent, swizzled slots)
#define VSTR 132    // V stays [key][dh] like R8 (scalar B loads, conflict-free)
#define PSTR 72     // 64 data + 8 pad   (pairs, no swizzle)

// projection tiling
#define PROJ_PAD 36

// scratch for q,k,v: [BATCH*SEQ, DH] fp32 each (static device mem — no allocs)
__device__ float g_q[BATCH * SEQ * DH];
__device__ float g_k[BATCH * SEQ * DH];
__device__ float g_v[BATCH * SEQ * DH];

// round-to-nearest fp32 -> tf32 bit pattern (RNA kills truncation bias)
__device__ __forceinline__ unsigned f2tf(float x) {
    unsigned u;
    asm("cvt.rna.tf32.f32 %0, %1;" : "=r"(u) : "f"(x));
    return u;
}
__device__ __forceinline__ unsigned fu(float x) { return __float_as_uint(x); }

__device__ __forceinline__ void mma_tf32(float c[4], const unsigned a[4], const unsigned b[2]) {
    asm volatile(
        "mma.sync.aligned.m16n8k8.row.col.f32.tf32.tf32.f32 "
        "{%0,%1,%2,%3}, {%4,%5,%6,%7}, {%8,%9}, {%0,%1,%2,%3};\n"
        : "+f"(c[0]), "+f"(c[1]), "+f"(c[2]), "+f"(c[3])
        : "r"(a[0]), "r"(a[1]), "r"(a[2]), "r"(a[3]), "r"(b[0]), "r"(b[1]));
}

// ---------------------------------------------------------------------------
// QKV projection (unchanged from R8 — ~30us, not the bottleneck)
// ---------------------------------------------------------------------------
__global__ void __launch_bounds__(256) qkv_proj_kernel(
    const float* __restrict__ x,
    const float* __restrict__ Wq,
    const float* __restrict__ Wk,
    const float* __restrict__ Wv)
{
    __shared__ float sA[128 * PROJ_PAD];
    __shared__ float sB[128 * PROJ_PAD];

    const float* W  = (blockIdx.y == 0) ? Wq : (blockIdx.y == 1) ? Wk : Wv;
    float*       out = (blockIdx.y == 0) ? g_q : (blockIdx.y == 1) ? g_k : g_v;

    const int m0   = blockIdx.x * 128;
    const int tid  = threadIdx.x;
    const int lane = tid & 31;
    const int w    = tid >> 5;
    const int wm   = w & 3;
    const int wn   = w >> 2;

    float acc[2][8][4];
    #pragma unroll
    for (int mt = 0; mt < 2; mt++)
        #pragma unroll
        for (int nt = 0; nt < 8; nt++)
            #pragma unroll
            for (int i = 0; i < 4; i++) acc[mt][nt][i] = 0.f;

    for (int kc = 0; kc < DE; kc += 32) {
        __syncthreads();
        #pragma unroll
        for (int i = 0; i < 4; i++) {
            const int idx = tid + i * 256;
            const int r = idx >> 3;
            const int c = (idx & 7) << 2;
            float4 v = *(const float4*)(x + (size_t)(m0 + r) * DE + kc + c);
            float* d = &sA[r * PROJ_PAD + c];
            d[0] = __uint_as_float(f2tf(v.x));
            d[1] = __uint_as_float(f2tf(v.y));
            d[2] = __uint_as_float(f2tf(v.z));
            d[3] = __uint_as_float(f2tf(v.w));
            float4 u = *(const float4*)(W + (size_t)r * DE + kc + c);
            float* e = &sB[r * PROJ_PAD + c];
            e[0] = __uint_as_float(f2tf(u.x));
            e[1] = __uint_as_float(f2tf(u.y));
            e[2] = __uint_as_float(f2tf(u.z));
            e[3] = __uint_as_float(f2tf(u.w));
        }
        __syncthreads();

        #pragma unroll
        for (int ks = 0; ks < 4; ks++) {
            const int c = ks * 8 + (lane & 3);
            unsigned a[2][4];
            #pragma unroll
            for (int mt = 0; mt < 2; mt++) {
                const int r = wm * 32 + mt * 16 + (lane >> 2);
                a[mt][0] = fu(sA[r * PROJ_PAD + c]);
                a[mt][1] = fu(sA[(r + 8) * PROJ_PAD + c]);
                a[mt][2] = fu(sA[r * PROJ_PAD + c + 4]);
                a[mt][3] = fu(sA[(r + 8) * PROJ_PAD + c + 4]);
            }
            #pragma unroll
            for (int nt = 0; nt < 8; nt++) {
                const int n = wn * 64 + nt * 8 + (lane >> 2);
                unsigned b[2];
                b[0] = fu(sB[n * PROJ_PAD + c]);
                b[1] = fu(sB[n * PROJ_PAD + c + 4]);
                mma_tf32(acc[0][nt], a[0], b);
                mma_tf32(acc[1][nt], a[1], b);
            }
        }
    }

    #pragma unroll
    for (int mt = 0; mt < 2; mt++) {
        const int r = m0 + wm * 32 + mt * 16 + (lane >> 2);
        #pragma unroll
        for (int nt = 0; nt < 8; nt++) {
            const int c = wn * 64 + nt * 8 + 2 * (lane & 3);
            *(float2*)(out + (size_t)r * DH + c)       = make_float2(acc[mt][nt][0], acc[mt][nt][1]);
            *(float2*)(out + (size_t)(r + 8) * DH + c) = make_float2(acc[mt][nt][2], acc[mt][nt][3]);
        }
    }
}

// ---------------------------------------------------------------------------
// Flash attention, 8 warps per CTA.
//   warp w: wr = w&3 (query row strip, 16 rows), wc = w>>2 (half of keys/cols)
//   QK^T : warp computes S[wr*16 .. +16][wc*32 .. +32]; row stats combined
//          across warp pairs via tiny smem arrays.
//   P@V  : warp accumulates over ITS key half for all 128 dh cols; the pair's
//          partial accs are summed once in the epilogue.
// Q/K/P use pair-packed k layouts: fragment (k,k+4) = one LDS.64.
// Packed chunk layout: chunk ch (8 k's) holds 4 float2 slots; pair i (=k%4)
// lives in slot s = (i + (ch>>2)) & 3 (swizzle makes packed STS conflict-free).
// ---------------------------------------------------------------------------
__global__ void __launch_bounds__(256, 2) attn_kernel(float* __restrict__ out)
{
    extern __shared__ float sm[];
    float* sQ  = sm;                    // [64][QSTR] packed (reused as acc-exchange in epilogue)
    float* sKV = sQ + BR * QSTR;        // K packed [64][QSTR]  /  V [64][VSTR]
    float* sP  = sKV + BC * QSTR;       // [64][PSTR] packed pairs (no swizzle)
    float* sRM = sP + BR * PSTR;        // [2][64] row-max exchange
    float* sRS = sRM + 128;             // [2][64] row-sum exchange

    const int b    = blockIdx.y;
    const int qt   = blockIdx.x;
    const int tid  = threadIdx.x;
    const int lane = tid & 31;
    const int w    = tid >> 5;
    const int wr   = w & 3;
    const int wc   = w >> 2;
    const int q4   = lane >> 2;     // quad row within strip
    const int kk   = lane & 3;      // k-slot within fragment

    const float* Qg = g_q + ((size_t)b * SEQ + (size_t)qt * BR) * DH;
    const float* Kg = g_k + (size_t)b * SEQ * DH;
    const float* Vg = g_v + (size_t)b * SEQ * DH;

    // 1/(sqrt(DH)*sqrt(DE)) * log2(e) folded into Q; softmax in exp2 domain
    const float qscale = 1.4426950408889634f / 362.03867196751236f;

    // ---- stage Q, pair-packed + swizzled: 64 rows x 16 chunks ----
    #pragma unroll
    for (int it = 0; it < 4; it++) {
        const int idx = tid + it * 256;
        const int r  = idx >> 4;
        const int ch = idx & 15;
        const float* g = Qg + (size_t)r * DH + ch * 8;
        float4 lo = *(const float4*)g;
        float4 hi = *(const float4*)(g + 4);
        float v[8] = {lo.x, lo.y, lo.z, lo.w, hi.x, hi.y, hi.z, hi.w};
        float* d = &sQ[r * QSTR + ch * 8];
        const int a = ch >> 2;
        #pragma unroll
        for (int i = 0; i < 4; i++) {
            const int s2 = (((i + a) & 3) << 1);
            *(float2*)(d + s2) = make_float2(
                __uint_as_float(f2tf(v[i]     * qscale)),
                __uint_as_float(f2tf(v[i + 4] * qscale)));
        }
    }

    float acc[16][4];
    #pragma unroll
    for (int nt = 0; nt < 16; nt++)
        #pragma unroll
        for (int i = 0; i < 4; i++) acc[nt][i] = 0.f;
    float m0f = -INFINITY, m1f = -INFINITY;
    float l0 = 0.f, l1 = 0.f;

    const float* Qrow0 = sQ + (wr * 16 + q4) * QSTR;
    const float* Qrow1 = Qrow0 + 8 * QSTR;
    float* Pr0 = sP + (wr * 16 + q4) * PSTR + wc * 32;
    float* Pr1 = Pr0 + 8 * PSTR;
    const int pos0 = (kk < 2) ? 4 * kk : 4 * kk - 7;   // packed P slot offsets
    const int rrow = wr * 16 + q4;

    for (int kt = 0; kt < SEQ / BC; kt++) {
        __syncthreads();   // S0: prior PV V-reads + stat reads done

        // ---- load K tile, pair-packed + swizzled ----
        const float* Kt = Kg + (size_t)kt * BC * DH;
        #pragma unroll
        for (int it = 0; it < 4; it++) {
            const int idx = tid + it * 256;
            const int r  = idx >> 4;
            const int ch = idx & 15;
            const float* g = Kt + (size_t)r * DH + ch * 8;
            float4 lo = *(const float4*)g;
            float4 hi = *(const float4*)(g + 4);
            float v[8] = {lo.x, lo.y, lo.z, lo.w, hi.x, hi.y, hi.z, hi.w};
            float* d = &sKV[r * QSTR + ch * 8];
            const int a = ch >> 2;
            #pragma unroll
            for (int i = 0; i < 4; i++) {
                const int s2 = (((i + a) & 3) << 1);
                *(float2*)(d + s2) = make_float2(
                    __uint_as_float(f2tf(v[i])),
                    __uint_as_float(f2tf(v[i + 4])));
            }
        }
        __syncthreads();   // S1: K ready

        // ---- S strip = Q[wr] K[wc]^T : 16x32, one LDS.64 per fragment ----
        float s[4][4];
        #pragma unroll
        for (int nt = 0; nt < 4; nt++)
            #pragma unroll
            for (int i = 0; i < 4; i++) s[nt][i] = 0.f;

        #pragma unroll
        for (int ks = 0; ks < 16; ks++) {
            const int off = ks * 8 + (((kk + (ks >> 2)) & 3) << 1);
            float2 a02 = *(const float2*)(Qrow0 + off);
            float2 a13 = *(const float2*)(Qrow1 + off);
            unsigned A[4] = {fu(a02.x), fu(a13.x), fu(a02.y), fu(a13.y)};
            #pragma unroll
            for (int nt = 0; nt < 4; nt++) {
                const int n = wc * 32 + nt * 8 + q4;
                float2 bp = *(const float2*)(sKV + n * QSTR + off);
                unsigned B[2] = {fu(bp.x), fu(bp.y)};
                mma_tf32(s[nt], A, B);
            }
        }
        __syncthreads();   // S2: all K reads done (V overwrites the buffer)

        // ---- start V tile load ([key][VSTR], as in R8 — conflict-free) ----
        const float* Vt = Vg + (size_t)kt * BC * DH;
        #pragma unroll
        for (int it = 0; it < 8; it++) {
            const int i = tid + it * 256;
            const int r = i >> 5;
            const int c = (i & 31) << 2;
            float4 v = *(const float4*)(Vt + (size_t)r * DH + c);
            float* d = &sKV[r * VSTR + c];
            d[0] = __uint_as_float(f2tf(v.x));
            d[1] = __uint_as_float(f2tf(v.y));
            d[2] = __uint_as_float(f2tf(v.z));
            d[3] = __uint_as_float(f2tf(v.w));
        }

        // ---- row max: warp-local then cross-pair via smem ----
        float rmax0 = -INFINITY, rmax1 = -INFINITY;
        #pragma unroll
        for (int nt = 0; nt < 4; nt++) {
            rmax0 = fmaxf(rmax0, fmaxf(s[nt][0], s[nt][1]));
            rmax1 = fmaxf(rmax1, fmaxf(s[nt][2], s[nt][3]));
        }
        rmax0 = fmaxf(rmax0, __shfl_xor_sync(0xffffffffu, rmax0, 1));
        rmax0 = fmaxf(rmax0, __shfl_xor_sync(0xffffffffu, rmax0, 2));
        rmax1 = fmaxf(rmax1, __shfl_xor_sync(0xffffffffu, rmax1, 1));
        rmax1 = fmaxf(rmax1, __shfl_xor_sync(0xffffffffu, rmax1, 2));
        if (kk == 0) {
            sRM[wc * 64 + rrow]     = rmax0;
            sRM[wc * 64 + rrow + 8] = rmax1;
        }
        __syncthreads();   // S3: sRM ready (V stores also all issued)

        const float om0 = sRM[(1 - wc) * 64 + rrow];
        const float om1 = sRM[(1 - wc) * 64 + rrow + 8];
        const float mnew0 = fmaxf(m0f, fmaxf(rmax0, om0));
        const float mnew1 = fmaxf(m1f, fmaxf(rmax1, om1));
        const float alpha0 = exp2f(m0f - mnew0);
        const float alpha1 = exp2f(m1f - mnew1);
        m0f = mnew0; m1f = mnew1;

        // ---- P = exp2(S - m), tf32-rounded BEFORE summing; packed store ----
        float rs0 = 0.f, rs1 = 0.f;
        #pragma unroll
        for (int nt = 0; nt < 4; nt++) {
            float p0 = __uint_as_float(f2tf(exp2f(s[nt][0] - mnew0)));
            float p1 = __uint_as_float(f2tf(exp2f(s[nt][1] - mnew0)));
            float p2 = __uint_as_float(f2tf(exp2f(s[nt][2] - mnew1)));
            float p3 = __uint_as_float(f2tf(exp2f(s[nt][3] - mnew1)));
            rs0 += p0 + p1;
            rs1 += p2 + p3;
            Pr0[nt * 8 + pos0]     = p0;
            Pr0[nt * 8 + pos0 + 2] = p1;
            Pr1[nt * 8 + pos0]     = p2;
            Pr1[nt * 8 + pos0 + 2] = p3;
        }
        rs0 += __shfl_xor_sync(0xffffffffu, rs0, 1);
        rs0 += __shfl_xor_sync(0xffffffffu, rs0, 2);
        rs1 += __shfl_xor_sync(0xffffffffu, rs1, 1);
        rs1 += __shfl_xor_sync(0xffffffffu, rs1, 2);
        if (kk == 0) {
            sRS[wc * 64 + rrow]     = rs0;
            sRS[wc * 64 + rrow + 8] = rs1;
        }

        // rescale running accumulator (valid for both key halves)
        #pragma unroll
        for (int nt = 0; nt < 16; nt++) {
            acc[nt][0] *= alpha0;
            acc[nt][1] *= alpha0;
            acc[nt][2] *= alpha1;
            acc[nt][3] *= alpha1;
        }
        __syncthreads();   // S4: sRS + P + V all visible

        l0 = l0 * alpha0 + rs0 + sRS[(1 - wc) * 64 + rrow];
        l1 = l1 * alpha1 + rs1 + sRS[(1 - wc) * 64 + rrow + 8];

        // ---- acc += P[:, wc-half] @ V[wc-half, :]  (warp's own key half) ----
        #pragma unroll
        for (int ksl = 0; ksl < 4; ksl++) {
            const int ks  = wc * 4 + ksl;
            const int off = ks * 8 + 2 * kk;
            float2 a02 = *(const float2*)(sP + rrow * PSTR + off);
            float2 a13 = *(const float2*)(sP + (rrow + 8) * PSTR + off);
            unsigned A[4] = {fu(a02.x), fu(a13.x), fu(a02.y), fu(a13.y)};
            const int c = ks * 8 + kk;
            #pragma unroll
            for (int nt = 0; nt < 16; nt++) {
                const int n = nt * 8 + q4;
                unsigned B[2] = {fu(sKV[c * VSTR + n]), fu(sKV[(c + 4) * VSTR + n])};
                mma_tf32(acc[nt], A, B);
            }
        }
    }

    // ---- epilogue: sum warp-pair partial accs, divide by l, store ----
    __syncthreads();
    float* e0 = sQ + rrow * VSTR;          // reuse Q buffer (64*132 <= 64*136)
    float* e1 = e0 + 8 * VSTR;
    if (wc == 1) {
        #pragma unroll
        for (int nt = 0; nt < 16; nt++) {
            const int c = nt * 8 + 2 * kk;
            *(float2*)(e0 + c) = make_float2(acc[nt][0], acc[nt][1]);
            *(float2*)(e1 + c) = make_float2(acc[nt][2], acc[nt][3]);
        }
    }
    __syncthreads();
    if (wc == 0) {
        const float inv0 = 1.f / l0;
        const float inv1 = 1.f / l1;
        const int r = qt * BR + rrow;
        float* Ob = out + (size_t)b * SEQ * DH;
        #pragma unroll
        for (int nt = 0; nt < 16; nt++) {
            const int c = nt * 8 + 2 * kk;
            float2 x0 = *(const float2*)(e0 + c);
            float2 x1 = *(const float2*)(e1 + c);
            *(float2*)(Ob + (size_t)r * DH + c) =
                make_float2((acc[nt][0] + x0.x) * inv0, (acc[nt][1] + x0.y) * inv0);
            *(float2*)(Ob + (size_t)(r + 8) * DH + c) =
                make_float2((acc[nt][2] + x1.x) * inv1, (acc[nt][3] + x1.y) * inv1);
        }
    }
}

// ---------------------------------------------------------------------------
extern "C" void kernel_launch(void* const* d_in, const int* in_sizes, int n_in,
                              void* d_out, int out_size)
{
    (void)in_sizes; (void)n_in; (void)out_size;
    const float* x  = (const float*)d_in[0];
    const float* Wq = (const float*)d_in[1];
    const float* Wk = (const float*)d_in[2];
    const float* Wv = (const float*)d_in[3];
    float* out = (float*)d_out;

    // sQ 64*136 + sKV 64*136 + sP 64*72 + sRM 128 + sRS 128 = 22272 floats
    const int attn_smem = (BR * QSTR + BC * QSTR + BR * PSTR + 256) * (int)sizeof(float); // 89088 B
    (void)cudaFuncSetAttribute(attn_kernel, cudaFuncAttributeMaxDynamicSharedMemorySize, attn_smem);

    qkv_proj_kernel<<<dim3((BATCH * SEQ) / 128, 3), 256>>>(x, Wq, Wk, Wv);
    attn_kernel<<<dim3(SEQ / BR, BATCH), 256, attn_smem>>>(out);
}

// round 12
// speedup vs baseline: 1.0147x; 1.0001x over previous
#include <cuda_runtime.h>
#include <cstdint>
#include <cstddef>

#define SEQ   4096
#define BATCH 4
#define DE    1024
#define DH    128

// flash-attention tiling
#define BR 64
#define BC 64

// packed k-dim row strides (floats)
#define QSTR 136    // 128 data + 8 pad  (pairs (k,k+4) adjacent, swizzled slots)
#define VSTR 132    // V stays [key][dh] like R8 (scalar B loads, conflict-free)
#define PSTR 72     // 64 data + 8 pad   (pairs, no swizzle)

// projection tiling
#define PROJ_PAD 36

// scratch for q,k,v: [BATCH*SEQ, DH] fp32 each (static device mem — no allocs)
__device__ float g_q[BATCH * SEQ * DH];
__device__ float g_k[BATCH * SEQ * DH];
__device__ float g_v[BATCH * SEQ * DH];

// round-to-nearest fp32 -> tf32 bit pattern (RNA kills truncation bias)
__device__ __forceinline__ unsigned f2tf(float x) {
    unsigned u;
    asm("cvt.rna.tf32.f32 %0, %1;" : "=r"(u) : "f"(x));
    return u;
}
__device__ __forceinline__ unsigned fu(float x) { return __float_as_uint(x); }

__device__ __forceinline__ void mma_tf32(float c[4], const unsigned a[4], const unsigned b[2]) {
    asm volatile(
        "mma.sync.aligned.m16n8k8.row.col.f32.tf32.tf32.f32 "
        "{%0,%1,%2,%3}, {%4,%5,%6,%7}, {%8,%9}, {%0,%1,%2,%3};\n"
        : "+f"(c[0]), "+f"(c[1]), "+f"(c[2]), "+f"(c[3])
        : "r"(a[0]), "r"(a[1]), "r"(a[2]), "r"(a[3]), "r"(b[0]), "r"(b[1]));
}

// ---------------------------------------------------------------------------
// QKV projection (unchanged from R8 — ~30us, not the bottleneck)
// ---------------------------------------------------------------------------
__global__ void __launch_bounds__(256) qkv_proj_kernel(
    const float* __restrict__ x,
    const float* __restrict__ Wq,
    const float* __restrict__ Wk,
    const float* __restrict__ Wv)
{
    __shared__ float sA[128 * PROJ_PAD];
    __shared__ float sB[128 * PROJ_PAD];

    const float* W  = (blockIdx.y == 0) ? Wq : (blockIdx.y == 1) ? Wk : Wv;
    float*       out = (blockIdx.y == 0) ? g_q : (blockIdx.y == 1) ? g_k : g_v;

    const int m0   = blockIdx.x * 128;
    const int tid  = threadIdx.x;
    const int lane = tid & 31;
    const int w    = tid >> 5;
    const int wm   = w & 3;
    const int wn   = w >> 2;

    float acc[2][8][4];
    #pragma unroll
    for (int mt = 0; mt < 2; mt++)
        #pragma unroll
        for (int nt = 0; nt < 8; nt++)
            #pragma unroll
            for (int i = 0; i < 4; i++) acc[mt][nt][i] = 0.f;

    for (int kc = 0; kc < DE; kc += 32) {
        __syncthreads();
        #pragma unroll
        for (int i = 0; i < 4; i++) {
            const int idx = tid + i * 256;
            const int r = idx >> 3;
            const int c = (idx & 7) << 2;
            float4 v = *(const float4*)(x + (size_t)(m0 + r) * DE + kc + c);
            float* d = &sA[r * PROJ_PAD + c];
            d[0] = __uint_as_float(f2tf(v.x));
            d[1] = __uint_as_float(f2tf(v.y));
            d[2] = __uint_as_float(f2tf(v.z));
            d[3] = __uint_as_float(f2tf(v.w));
            float4 u = *(const float4*)(W + (size_t)r * DE + kc + c);
            float* e = &sB[r * PROJ_PAD + c];
            e[0] = __uint_as_float(f2tf(u.x));
            e[1] = __uint_as_float(f2tf(u.y));
            e[2] = __uint_as_float(f2tf(u.z));
            e[3] = __uint_as_float(f2tf(u.w));
        }
        __syncthreads();

        #pragma unroll
        for (int ks = 0; ks < 4; ks++) {
            const int c = ks * 8 + (lane & 3);
            unsigned a[2][4];
            #pragma unroll
            for (int mt = 0; mt < 2; mt++) {
                const int r = wm * 32 + mt * 16 + (lane >> 2);
                a[mt][0] = fu(sA[r * PROJ_PAD + c]);
                a[mt][1] = fu(sA[(r + 8) * PROJ_PAD + c]);
                a[mt][2] = fu(sA[r * PROJ_PAD + c + 4]);
                a[mt][3] = fu(sA[(r + 8) * PROJ_PAD + c + 4]);
            }
            #pragma unroll
            for (int nt = 0; nt < 8; nt++) {
                const int n = wn * 64 + nt * 8 + (lane >> 2);
                unsigned b[2];
                b[0] = fu(sB[n * PROJ_PAD + c]);
                b[1] = fu(sB[n * PROJ_PAD + c + 4]);
                mma_tf32(acc[0][nt], a[0], b);
                mma_tf32(acc[1][nt], a[1], b);
            }
        }
    }

    #pragma unroll
    for (int mt = 0; mt < 2; mt++) {
        const int r = m0 + wm * 32 + mt * 16 + (lane >> 2);
        #pragma unroll
        for (int nt = 0; nt < 8; nt++) {
            const int c = wn * 64 + nt * 8 + 2 * (lane & 3);
            *(float2*)(out + (size_t)r * DH + c)       = make_float2(acc[mt][nt][0], acc[mt][nt][1]);
            *(float2*)(out + (size_t)(r + 8) * DH + c) = make_float2(acc[mt][nt][2], acc[mt][nt][3]);
        }
    }
}

// ---------------------------------------------------------------------------
// Flash attention, 8 warps per CTA.
//   warp w: wr = w&3 (query row strip, 16 rows), wc = w>>2 (half of keys/cols)
//   QK^T : warp computes S[wr*16 .. +16][wc*32 .. +32]; row stats combined
//          across warp pairs via tiny smem arrays.
//   P@V  : warp accumulates over ITS key half for all 128 dh cols; the pair's
//          partial accs are summed once in the epilogue.
// Q/K/P use pair-packed k layouts: fragment (k,k+4) = one LDS.64.
// Packed chunk layout: chunk ch (8 k's) holds 4 float2 slots; pair i (=k%4)
// lives in slot s = (i + (ch>>2)) & 3 (swizzle makes packed STS conflict-free).
// ---------------------------------------------------------------------------
__global__ void __launch_bounds__(256, 2) attn_kernel(float* __restrict__ out)
{
    extern __shared__ float sm[];
    float* sQ  = sm;                    // [64][QSTR] packed (reused as acc-exchange in epilogue)
    float* sKV = sQ + BR * QSTR;        // K packed [64][QSTR]  /  V [64][VSTR]
    float* sP  = sKV + BC * QSTR;       // [64][PSTR] packed pairs (no swizzle)
    float* sRM = sP + BR * PSTR;        // [2][64] row-max exchange
    float* sRS = sRM + 128;             // [2][64] row-sum exchange

    const int b    = blockIdx.y;
    const int qt   = blockIdx.x;
    const int tid  = threadIdx.x;
    const int lane = tid & 31;
    const int w    = tid >> 5;
    const int wr   = w & 3;
    const int wc   = w >> 2;
    const int q4   = lane >> 2;     // quad row within strip
    const int kk   = lane & 3;      // k-slot within fragment

    const float* Qg = g_q + ((size_t)b * SEQ + (size_t)qt * BR) * DH;
    const float* Kg = g_k + (size_t)b * SEQ * DH;
    const float* Vg = g_v + (size_t)b * SEQ * DH;

    // 1/(sqrt(DH)*sqrt(DE)) * log2(e) folded into Q; softmax in exp2 domain
    const float qscale = 1.4426950408889634f / 362.03867196751236f;

    // ---- stage Q, pair-packed + swizzled: 64 rows x 16 chunks ----
    #pragma unroll
    for (int it = 0; it < 4; it++) {
        const int idx = tid + it * 256;
        const int r  = idx >> 4;
        const int ch = idx & 15;
        const float* g = Qg + (size_t)r * DH + ch * 8;
        float4 lo = *(const float4*)g;
        float4 hi = *(const float4*)(g + 4);
        float v[8] = {lo.x, lo.y, lo.z, lo.w, hi.x, hi.y, hi.z, hi.w};
        float* d = &sQ[r * QSTR + ch * 8];
        const int a = ch >> 2;
        #pragma unroll
        for (int i = 0; i < 4; i++) {
            const int s2 = (((i + a) & 3) << 1);
            *(float2*)(d + s2) = make_float2(
                __uint_as_float(f2tf(v[i]     * qscale)),
                __uint_as_float(f2tf(v[i + 4] * qscale)));
        }
    }

    float acc[16][4];
    #pragma unroll
    for (int nt = 0; nt < 16; nt++)
        #pragma unroll
        for (int i = 0; i < 4; i++) acc[nt][i] = 0.f;
    float m0f = -INFINITY, m1f = -INFINITY;
    float l0 = 0.f, l1 = 0.f;

    const float* Qrow0 = sQ + (wr * 16 + q4) * QSTR;
    const float* Qrow1 = Qrow0 + 8 * QSTR;
    float* Pr0 = sP + (wr * 16 + q4) * PSTR + wc * 32;
    float* Pr1 = Pr0 + 8 * PSTR;
    const int pos0 = (kk < 2) ? 4 * kk : 4 * kk - 7;   // packed P slot offsets
    const int rrow = wr * 16 + q4;

    for (int kt = 0; kt < SEQ / BC; kt++) {
        __syncthreads();   // S0: prior PV V-reads + stat reads done

        // ---- load K tile, pair-packed + swizzled ----
        const float* Kt = Kg + (size_t)kt * BC * DH;
        #pragma unroll
        for (int it = 0; it < 4; it++) {
            const int idx = tid + it * 256;
            const int r  = idx >> 4;
            const int ch = idx & 15;
            const float* g = Kt + (size_t)r * DH + ch * 8;
            float4 lo = *(const float4*)g;
            float4 hi = *(const float4*)(g + 4);
            float v[8] = {lo.x, lo.y, lo.z, lo.w, hi.x, hi.y, hi.z, hi.w};
            float* d = &sKV[r * QSTR + ch * 8];
            const int a = ch >> 2;
            #pragma unroll
            for (int i = 0; i < 4; i++) {
                const int s2 = (((i + a) & 3) << 1);
                *(float2*)(d + s2) = make_float2(
                    __uint_as_float(f2tf(v[i])),
                    __uint_as_float(f2tf(v[i + 4])));
            }
        }
        __syncthreads();   // S1: K ready

        // ---- S strip = Q[wr] K[wc]^T : 16x32, one LDS.64 per fragment ----
        float s[4][4];
        #pragma unroll
        for (int nt = 0; nt < 4; nt++)
            #pragma unroll
            for (int i = 0; i < 4; i++) s[nt][i] = 0.f;

        #pragma unroll
        for (int ks = 0; ks < 16; ks++) {
            const int off = ks * 8 + (((kk + (ks >> 2)) & 3) << 1);
            float2 a02 = *(const float2*)(Qrow0 + off);
            float2 a13 = *(const float2*)(Qrow1 + off);
            unsigned A[4] = {fu(a02.x), fu(a13.x), fu(a02.y), fu(a13.y)};
            #pragma unroll
            for (int nt = 0; nt < 4; nt++) {
                const int n = wc * 32 + nt * 8 + q4;
                float2 bp = *(const float2*)(sKV + n * QSTR + off);
                unsigned B[2] = {fu(bp.x), fu(bp.y)};
                mma_tf32(s[nt], A, B);
            }
        }
        __syncthreads();   // S2: all K reads done (V overwrites the buffer)

        // ---- start V tile load ([key][VSTR], as in R8 — conflict-free) ----
        const float* Vt = Vg + (size_t)kt * BC * DH;
        #pragma unroll
        for (int it = 0; it < 8; it++) {
            const int i = tid + it * 256;
            const int r = i >> 5;
            const int c = (i & 31) << 2;
            float4 v = *(const float4*)(Vt + (size_t)r * DH + c);
            float* d = &sKV[r * VSTR + c];
            d[0] = __uint_as_float(f2tf(v.x));
            d[1] = __uint_as_float(f2tf(v.y));
            d[2] = __uint_as_float(f2tf(v.z));
            d[3] = __uint_as_float(f2tf(v.w));
        }

        // ---- row max: warp-local then cross-pair via smem ----
        float rmax0 = -INFINITY, rmax1 = -INFINITY;
        #pragma unroll
        for (int nt = 0; nt < 4; nt++) {
            rmax0 = fmaxf(rmax0, fmaxf(s[nt][0], s[nt][1]));
            rmax1 = fmaxf(rmax1, fmaxf(s[nt][2], s[nt][3]));
        }
        rmax0 = fmaxf(rmax0, __shfl_xor_sync(0xffffffffu, rmax0, 1));
        rmax0 = fmaxf(rmax0, __shfl_xor_sync(0xffffffffu, rmax0, 2));
        rmax1 = fmaxf(rmax1, __shfl_xor_sync(0xffffffffu, rmax1, 1));
        rmax1 = fmaxf(rmax1, __shfl_xor_sync(0xffffffffu, rmax1, 2));
        if (kk == 0) {
            sRM[wc * 64 + rrow]     = rmax0;
            sRM[wc * 64 + rrow + 8] = rmax1;
        }
        __syncthreads();   // S3: sRM ready (V stores also all issued)

        const float om0 = sRM[(1 - wc) * 64 + rrow];
        const float om1 = sRM[(1 - wc) * 64 + rrow + 8];
        const float mnew0 = fmaxf(m0f, fmaxf(rmax0, om0));
        const float mnew1 = fmaxf(m1f, fmaxf(rmax1, om1));
        const float alpha0 = exp2f(m0f - mnew0);
        const float alpha1 = exp2f(m1f - mnew1);
        m0f = mnew0; m1f = mnew1;

        // ---- P = exp2(S - m), tf32-rounded BEFORE summing; packed store ----
        float rs0 = 0.f, rs1 = 0.f;
        #pragma unroll
        for (int nt = 0; nt < 4; nt++) {
            float p0 = __uint_as_float(f2tf(exp2f(s[nt][0] - mnew0)));
            float p1 = __uint_as_float(f2tf(exp2f(s[nt][1] - mnew0)));
            float p2 = __uint_as_float(f2tf(exp2f(s[nt][2] - mnew1)));
            float p3 = __uint_as_float(f2tf(exp2f(s[nt][3] - mnew1)));
            rs0 += p0 + p1;
            rs1 += p2 + p3;
            Pr0[nt * 8 + pos0]     = p0;
            Pr0[nt * 8 + pos0 + 2] = p1;
            Pr1[nt * 8 + pos0]     = p2;
            Pr1[nt * 8 + pos0 + 2] = p3;
        }
        rs0 += __shfl_xor_sync(0xffffffffu, rs0, 1);
        rs0 += __shfl_xor_sync(0xffffffffu, rs0, 2);
        rs1 += __shfl_xor_sync(0xffffffffu, rs1, 1);
        rs1 += __shfl_xor_sync(0xffffffffu, rs1, 2);
        if (kk == 0) {
            sRS[wc * 64 + rrow]     = rs0;
            sRS[wc * 64 + rrow + 8] = rs1;
        }

        // rescale running accumulator (valid for both key halves)
        #pragma unroll
        for (int nt = 0; nt < 16; nt++) {
            acc[nt][0] *= alpha0;
            acc[nt][1] *= alpha0;
            acc[nt][2] *= alpha1;
            acc[nt][3] *= alpha1;
        }
        __syncthreads();   // S4: sRS + P + V all visible

        l0 = l0 * alpha0 + rs0 + sRS[(1 - wc) * 64 + rrow];
        l1 = l1 * alpha1 + rs1 + sRS[(1 - wc) * 64 + rrow + 8];

        // ---- acc += P[:, wc-half] @ V[wc-half, :]  (warp's own key half) ----
        #pragma unroll
        for (int ksl = 0; ksl < 4; ksl++) {
            const int ks  = wc * 4 + ksl;
            const int off = ks * 8 + 2 * kk;
            float2 a02 = *(const float2*)(sP + rrow * PSTR + off);
            float2 a13 = *(const float2*)(sP + (rrow + 8) * PSTR + off);
            unsigned A[4] = {fu(a02.x), fu(a13.x), fu(a02.y), fu(a13.y)};
            const int c = ks * 8 + kk;
            #pragma unroll
            for (int nt = 0; nt < 16; nt++) {
                const int n = nt * 8 + q4;
                unsigned B[2] = {fu(sKV[c * VSTR + n]), fu(sKV[(c + 4) * VSTR + n])};
                mma_tf32(acc[nt], A, B);
            }
        }
    }

    // ---- epilogue: sum warp-pair partial accs, divide by l, store ----
    __syncthreads();
    float* e0 = sQ + rrow * VSTR;          // reuse Q buffer (64*132 <= 64*136)
    float* e1 = e0 + 8 * VSTR;
    if (wc == 1) {
        #pragma unroll
        for (int nt = 0; nt < 16; nt++) {
            const int c = nt * 8 + 2 * kk;
            *(float2*)(e0 + c) = make_float2(acc[nt][0], acc[nt][1]);
            *(float2*)(e1 + c) = make_float2(acc[nt][2], acc[nt][3]);
        }
    }
    __syncthreads();
    if (wc == 0) {
        const float inv0 = 1.f / l0;
        const float inv1 = 1.f / l1;
        const int r = qt * BR + rrow;
        float* Ob = out + (size_t)b * SEQ * DH;
        #pragma unroll
        for (int nt = 0; nt < 16; nt++) {
            const int c = nt * 8 + 2 * kk;
            float2 x0 = *(const float2*)(e0 + c);
            float2 x1 = *(const float2*)(e1 + c);
            *(float2*)(Ob + (size_t)r * DH + c) =
                make_float2((acc[nt][0] + x0.x) * inv0, (acc[nt][1] + x0.y) * inv0);
            *(float2*)(Ob + (size_t)(r + 8) * DH + c) =
                make_float2((acc[nt][2] + x1.x) * inv1, (acc[nt][3] + x1.y) * inv1);
        }
    }
}

// ---------------------------------------------------------------------------
extern "C" void kernel_launch(void* const* d_in, const int* in_sizes, int n_in,
                              void* d_out, int out_size)
{
    (void)in_sizes; (void)n_in; (void)out_size;
    const float* x  = (const float*)d_in[0];
    const float* Wq = (const float*)d_in[1];
    const float* Wk = (const float*)d_in[2];
    const float* Wv = (const float*)d_in[3];
    float* out = (float*)d_out;

    // sQ 64*136 + sKV 64*136 + sP 64*72 + sRM 128 + sRS 128 = 22272 floats
    const int attn_smem = (BR * QSTR + BC * QSTR + BR * PSTR + 256) * (int)sizeof(float); // 89088 B
    (void)cudaFuncSetAttribute(attn_kernel, cudaFuncAttributeMaxDynamicSharedMemorySize, attn_smem);

    qkv_proj_kernel<<<dim3((BATCH * SEQ) / 128, 3), 256>>>(x, Wq, Wk, Wv);
    attn_kernel<<<dim3(SEQ / BR, BATCH), 256, attn_smem>>>(out);
}